// round 3
// baseline (speedup 1.0000x reference)
#include <cuda_runtime.h>
#include <cstdint>

// Inverse 2D Haar DWT, output-centric, 256-bit stores (sm_100+).
//
// Inputs: 4 x (4,64,256,256) fp32.  Output: (4,64,512,512) fp32.
//
// One thread handles one float4 (4 consecutive cols) from each band and
// writes one 32B (v8.f32) store per output row:
//   even row 2h  : {a0,b0,a1,b1,a2,b2,a3,b3}
//   odd  row 2h+1: {c0,d0,c1,d1,c2,d2,c3,d3}
//
// Warp-wide: loads 4 x 512B contiguous, stores 2 x 1024B contiguous.
// All full 128B sectors; streaming (.cs) hints since there is zero reuse.

static constexpr int W4_IN  = 256 / 4;   // 64 float4 per input row
static constexpr int H_IN   = 256;
static constexpr int W_OUT  = 512;       // floats per output row
static constexpr int PLANE_OUT = 512 * 512;

__device__ __forceinline__ void stg_cs_v8(float* p,
                                          float v0, float v1, float v2, float v3,
                                          float v4, float v5, float v6, float v7)
{
    asm volatile("st.global.cs.v8.f32 [%0], {%1,%2,%3,%4,%5,%6,%7,%8};"
                 :: "l"(p),
                    "f"(v0), "f"(v1), "f"(v2), "f"(v3),
                    "f"(v4), "f"(v5), "f"(v6), "f"(v7)
                 : "memory");
}

__global__ __launch_bounds__(256)
void haar_idwt2_kernel(const float4* __restrict__ ll,
                       const float4* __restrict__ lh,
                       const float4* __restrict__ hl,
                       const float4* __restrict__ hh,
                       float* __restrict__ out,
                       int n_f4)  // total float4 count = 4*64*256*64
{
    int f = blockIdx.x * blockDim.x + threadIdx.x;
    if (f >= n_f4) return;

    // f -> (plane, h, col4)
    int col4  = f & (W4_IN - 1);     // f % 64
    int r     = f >> 6;
    int h     = r & (H_IN - 1);      // r % 256
    int plane = r >> 8;

    float4 vll = __ldcs(&ll[f]);
    float4 vlh = __ldcs(&lh[f]);
    float4 vhl = __ldcs(&hl[f]);
    float4 vhh = __ldcs(&hh[f]);

    float a0 = (vll.x + vlh.x + vhl.x + vhh.x) * 0.5f;
    float b0 = (vll.x + vlh.x - vhl.x - vhh.x) * 0.5f;
    float c0 = (vll.x - vlh.x + vhl.x - vhh.x) * 0.5f;
    float d0 = (vll.x - vlh.x - vhl.x + vhh.x) * 0.5f;

    float a1 = (vll.y + vlh.y + vhl.y + vhh.y) * 0.5f;
    float b1 = (vll.y + vlh.y - vhl.y - vhh.y) * 0.5f;
    float c1 = (vll.y - vlh.y + vhl.y - vhh.y) * 0.5f;
    float d1 = (vll.y - vlh.y - vhl.y + vhh.y) * 0.5f;

    float a2 = (vll.z + vlh.z + vhl.z + vhh.z) * 0.5f;
    float b2 = (vll.z + vlh.z - vhl.z - vhh.z) * 0.5f;
    float c2 = (vll.z - vlh.z + vhl.z - vhh.z) * 0.5f;
    float d2 = (vll.z - vlh.z - vhl.z + vhh.z) * 0.5f;

    float a3 = (vll.w + vlh.w + vhl.w + vhh.w) * 0.5f;
    float b3 = (vll.w + vlh.w - vhl.w - vhh.w) * 0.5f;
    float c3 = (vll.w - vlh.w + vhl.w - vhh.w) * 0.5f;
    float d3 = (vll.w - vlh.w - vhl.w + vhh.w) * 0.5f;

    // Output float offsets: input col4 covers input cols 4c..4c+3
    // -> output cols 8c..8c+7 on rows 2h and 2h+1.
    int base0 = plane * PLANE_OUT + (2 * h) * W_OUT + 8 * col4;  // even row
    int base1 = base0 + W_OUT;                                    // odd row

    stg_cs_v8(out + base0, a0, b0, a1, b1, a2, b2, a3, b3);
    stg_cs_v8(out + base1, c0, d0, c1, d1, c2, d2, c3, d3);
}

extern "C" void kernel_launch(void* const* d_in, const int* in_sizes, int n_in,
                              void* d_out, int out_size)
{
    const float4* ll = (const float4*)d_in[0];
    const float4* lh = (const float4*)d_in[1];
    const float4* hl = (const float4*)d_in[2];
    const float4* hh = (const float4*)d_in[3];
    float* out = (float*)d_out;

    int n_f4 = in_sizes[0] / 4;       // 4,194,304
    int threads = 256;
    int blocks = (n_f4 + threads - 1) / threads;

    haar_idwt2_kernel<<<blocks, threads>>>(ll, lh, hl, hh, out, n_f4);
}

// round 4
// speedup vs baseline: 1.0078x; 1.0078x over previous
#include <cuda_runtime.h>
#include <cstdint>

// Inverse 2D Haar DWT, output-centric (R2 shape) with doubled per-thread MLP.
//
// Inputs: 4 x (4,64,256,256) fp32.  Output: (4,64,512,512) fp32.
//
// Each thread handles TWO float2 units: index f in the first half of the
// flattened input and f + n/2 in the second half. All 8 loads (4 bands x 2
// units) are issued before dependent math/stores -> 8 outstanding LDG.64
// per thread, keeping DRAM queues fuller.
//
// Per unit (same as R2, which achieved 74.3us / 82% DRAM):
//   even output row 2h : {a_j, b_j, a_{j+1}, b_{j+1}}   (one STG.128)
//   odd  output row 2h+1: {c_j, d_j, c_{j+1}, d_{j+1}}   (one STG.128)
// Warp-wide: loads 32 x 8B contiguous, stores 32 x 16B contiguous — all full
// 128B sectors. Streaming (.cs) hints, zero reuse.

static constexpr int W2_IN  = 256 / 2;        // 128 float2 per input row
static constexpr int H_IN   = 256;
static constexpr int W4_OUT = 512 / 4;        // 128 float4 per output row
static constexpr int PLANE_OUT_F4 = 512 * 512 / 4;  // 65536

__device__ __forceinline__ void haar_unit(float2 vll, float2 vlh,
                                          float2 vhl, float2 vhh,
                                          int f, float4* __restrict__ out)
{
    int col2  = f & (W2_IN - 1);
    int r     = f >> 7;
    int h     = r & (H_IN - 1);
    int plane = r >> 8;

    float a0 = (vll.x + vlh.x + vhl.x + vhh.x) * 0.5f;
    float b0 = (vll.x + vlh.x - vhl.x - vhh.x) * 0.5f;
    float c0 = (vll.x - vlh.x + vhl.x - vhh.x) * 0.5f;
    float d0 = (vll.x - vlh.x - vhl.x + vhh.x) * 0.5f;

    float a1 = (vll.y + vlh.y + vhl.y + vhh.y) * 0.5f;
    float b1 = (vll.y + vlh.y - vhl.y - vhh.y) * 0.5f;
    float c1 = (vll.y - vlh.y + vhl.y - vhh.y) * 0.5f;
    float d1 = (vll.y - vlh.y - vhl.y + vhh.y) * 0.5f;

    int idx0 = plane * PLANE_OUT_F4 + (2 * h) * W4_OUT + col2;  // even row
    int idx1 = idx0 + W4_OUT;                                   // odd row

    __stcs(&out[idx0], make_float4(a0, b0, a1, b1));
    __stcs(&out[idx1], make_float4(c0, d0, c1, d1));
}

__global__ __launch_bounds__(256)
void haar_idwt2_kernel(const float2* __restrict__ ll,
                       const float2* __restrict__ lh,
                       const float2* __restrict__ hl,
                       const float2* __restrict__ hh,
                       float4* __restrict__ out,
                       int half_n_f2)  // n_f2 / 2 = 4,194,304
{
    int f0 = blockIdx.x * blockDim.x + threadIdx.x;
    if (f0 >= half_n_f2) return;
    int f1 = f0 + half_n_f2;

    // Front-batch all 8 loads (independent -> 8 outstanding LDG.64)
    float2 vll0 = __ldcs(&ll[f0]);
    float2 vlh0 = __ldcs(&lh[f0]);
    float2 vhl0 = __ldcs(&hl[f0]);
    float2 vhh0 = __ldcs(&hh[f0]);
    float2 vll1 = __ldcs(&ll[f1]);
    float2 vlh1 = __ldcs(&lh[f1]);
    float2 vhl1 = __ldcs(&hl[f1]);
    float2 vhh1 = __ldcs(&hh[f1]);

    haar_unit(vll0, vlh0, vhl0, vhh0, f0, out);
    haar_unit(vll1, vlh1, vhl1, vhh1, f1, out);
}

extern "C" void kernel_launch(void* const* d_in, const int* in_sizes, int n_in,
                              void* d_out, int out_size)
{
    const float2* ll = (const float2*)d_in[0];
    const float2* lh = (const float2*)d_in[1];
    const float2* hl = (const float2*)d_in[2];
    const float2* hh = (const float2*)d_in[3];
    float4* out = (float4*)d_out;

    int half_n_f2 = in_sizes[0] / 4;   // (n/2)/2 = 4,194,304
    int threads = 256;
    int blocks = (half_n_f2 + threads - 1) / threads;

    haar_idwt2_kernel<<<blocks, threads>>>(ll, lh, hl, hh, out, half_n_f2);
}